// round 1
// baseline (speedup 1.0000x reference)
#include <cuda_runtime.h>
#include <math.h>

// Scratch (no cudaMalloc allowed)
__device__ float g_feats[32 * 1280];   // [B, (K+1)*C] pooled means
__device__ float g_w1[32 * 256];       // [B, C] sigmoid self-gate
__device__ float g_w2[32 * 4 * 256];   // [B, K, C] softmax branch gates

#define B_ 32
#define C_ 256
#define K_ 4
#define HW_ 1024
#define MID_ 32
#define FEAT_ 1280   // (K+1)*C

// ---------------- Kernel 1: global average pool over H*W for 5 tensors ----------------
// One warp per (b, slot, c) row of 1024 contiguous floats. 40960 warps total.
__global__ void k_means(const float* __restrict__ y,
                        const float* __restrict__ x0,
                        const float* __restrict__ x1,
                        const float* __restrict__ x2,
                        const float* __restrict__ x3) {
    int warp = (blockIdx.x * blockDim.x + threadIdx.x) >> 5;
    int lane = threadIdx.x & 31;
    if (warp >= B_ * FEAT_) return;
    int b = warp / FEAT_;
    int j = warp - b * FEAT_;       // slot*256 + c
    int slot = j >> 8;
    int c = j & 255;
    const float* base;
    switch (slot) {
        case 0: base = y;  break;
        case 1: base = x0; break;
        case 2: base = x1; break;
        case 3: base = x2; break;
        default: base = x3; break;
    }
    const float4* p = reinterpret_cast<const float4*>(base + (size_t)(b * C_ + c) * HW_);
    float s = 0.f;
#pragma unroll
    for (int i = 0; i < 8; i++) {        // 8 * 32 lanes * 4 floats = 1024
        float4 v = p[lane + i * 32];
        s += (v.x + v.y) + (v.z + v.w);
    }
#pragma unroll
    for (int o = 16; o; o >>= 1) s += __shfl_xor_sync(0xffffffffu, s, o);
    if (lane == 0) g_feats[warp] = s * (1.0f / 1024.0f);
}

// ---------------- Kernel 2: gate MLP (GEMM -> BN -> ReLU -> GEMM -> act) ----------------
// One block per batch element. 256 threads.
__global__ void k_gate(const float* __restrict__ conv1_w,   // [32,1280]
                       const float* __restrict__ bn_gamma,
                       const float* __restrict__ bn_beta,
                       const float* __restrict__ bn_mean,
                       const float* __restrict__ bn_var,
                       const float* __restrict__ conv2_w,   // [1280,32]
                       const float* __restrict__ conv2_b) { // [1280]
    __shared__ float sf[FEAT_];
    __shared__ float sh[MID_];
    int b = blockIdx.x;
    int t = threadIdx.x;

    for (int i = t; i < FEAT_; i += 256) sf[i] = g_feats[b * FEAT_ + i];
    __syncthreads();

    int warp = t >> 5, lane = t & 31;
    // GEMM1: each warp computes 4 of the 32 mid channels
#pragma unroll
    for (int mi = 0; mi < 4; mi++) {
        int mid = warp * 4 + mi;
        const float* wr = conv1_w + mid * FEAT_;
        float s = 0.f;
#pragma unroll
        for (int j0 = 0; j0 < FEAT_; j0 += 32) s = fmaf(sf[j0 + lane], wr[j0 + lane], s);
#pragma unroll
        for (int o = 16; o; o >>= 1) s += __shfl_xor_sync(0xffffffffu, s, o);
        if (lane == 0) {
            float hv = (s - bn_mean[mid]) * (bn_gamma[mid] * rsqrtf(bn_var[mid] + 1e-5f))
                       + bn_beta[mid];
            sh[mid] = fmaxf(hv, 0.f);
        }
    }
    __syncthreads();

    // GEMM2: thread t owns channel c=t across all 5 slots (j = m*256 + t)
    float v[5];
#pragma unroll
    for (int m = 0; m < 5; m++) {
        int j = m * 256 + t;
        float s = conv2_b[j];
        const float* wr = conv2_w + j * MID_;
#pragma unroll
        for (int mid = 0; mid < MID_; mid++) s = fmaf(sh[mid], wr[mid], s);
        v[m] = s;
    }
    // slot 0 -> sigmoid self gate
    g_w1[b * C_ + t] = 1.0f / (1.0f + expf(-v[0]));
    // slots 1..4 -> softmax over K
    float mx = fmaxf(fmaxf(v[1], v[2]), fmaxf(v[3], v[4]));
    float e1 = expf(v[1] - mx), e2 = expf(v[2] - mx);
    float e3 = expf(v[3] - mx), e4 = expf(v[4] - mx);
    float inv = 1.0f / (e1 + e2 + e3 + e4);
    int base = b * K_ * C_ + t;
    g_w2[base + 0 * C_] = e1 * inv;
    g_w2[base + 1 * C_] = e2 * inv;
    g_w2[base + 2 * C_] = e3 * inv;
    g_w2[base + 3 * C_] = e4 * inv;
}

// ---------------- Kernel 3: apply gates (streaming, float4) ----------------
__global__ void k_apply(const float* __restrict__ y,
                        const float* __restrict__ x0,
                        const float* __restrict__ x1,
                        const float* __restrict__ x2,
                        const float* __restrict__ x3,
                        float* __restrict__ out) {
    int i = blockIdx.x * blockDim.x + threadIdx.x;   // float4 index, total 2097152
    int bc = i >> 8;                                 // 256 float4 per (b,c) row
    int b = bc >> 8;
    int c = bc & 255;
    float w1 = g_w1[bc];
    int base = b * K_ * C_ + c;
    float a0 = g_w2[base + 0 * C_];
    float a1 = g_w2[base + 1 * C_];
    float a2 = g_w2[base + 2 * C_];
    float a3 = g_w2[base + 3 * C_];

    float4 yv = reinterpret_cast<const float4*>(y)[i];
    float4 v0 = reinterpret_cast<const float4*>(x0)[i];
    float4 v1 = reinterpret_cast<const float4*>(x1)[i];
    float4 v2 = reinterpret_cast<const float4*>(x2)[i];
    float4 v3 = reinterpret_cast<const float4*>(x3)[i];

    float4 r;
    r.x = fmaf(yv.x, w1, fmaf(a0, v0.x, fmaf(a1, v1.x, fmaf(a2, v2.x, a3 * v3.x))));
    r.y = fmaf(yv.y, w1, fmaf(a0, v0.y, fmaf(a1, v1.y, fmaf(a2, v2.y, a3 * v3.y))));
    r.z = fmaf(yv.z, w1, fmaf(a0, v0.z, fmaf(a1, v1.z, fmaf(a2, v2.z, a3 * v3.z))));
    r.w = fmaf(yv.w, w1, fmaf(a0, v0.w, fmaf(a1, v1.w, fmaf(a2, v2.w, a3 * v3.w))));
    reinterpret_cast<float4*>(out)[i] = r;
}

extern "C" void kernel_launch(void* const* d_in, const int* in_sizes, int n_in,
                              void* d_out, int out_size) {
    const float* y       = (const float*)d_in[0];
    const float* x0      = (const float*)d_in[1];
    const float* x1      = (const float*)d_in[2];
    const float* x2      = (const float*)d_in[3];
    const float* x3      = (const float*)d_in[4];
    const float* conv1_w = (const float*)d_in[5];
    const float* bn_g    = (const float*)d_in[6];
    const float* bn_b    = (const float*)d_in[7];
    const float* bn_m    = (const float*)d_in[8];
    const float* bn_v    = (const float*)d_in[9];
    const float* conv2_w = (const float*)d_in[10];
    const float* conv2_b = (const float*)d_in[11];
    float* out = (float*)d_out;

    // 40960 warps, 8 warps/block -> 5120 blocks
    k_means<<<5120, 256>>>(y, x0, x1, x2, x3);
    k_gate<<<32, 256>>>(conv1_w, bn_g, bn_b, bn_m, bn_v, conv2_w, conv2_b);
    // 2097152 float4 / 256 threads -> 8192 blocks
    k_apply<<<8192, 256>>>(y, x0, x1, x2, x3, out);
}

// round 2
// speedup vs baseline: 1.1125x; 1.1125x over previous
#include <cuda_runtime.h>
#include <math.h>

// Scratch (no cudaMalloc allowed)
__device__ float g_feats[32 * 1280];   // [B, (K+1)*C] pooled means
__device__ float g_w1[32 * 256];       // [B, C] sigmoid self-gate
__device__ float g_w2[32 * 4 * 256];   // [B, K, C] softmax branch gates

#define B_ 32
#define C_ 256
#define K_ 4
#define HW_ 1024
#define MID_ 32
#define FEAT_ 1280   // (K+1)*C

// ---------------- Kernel 1: global average pool over H*W for 5 tensors ----------------
// One warp per (b, slot, c) row of 1024 contiguous floats. 40960 warps total.
// Forward traversal: tail of the address range is L2-resident when this finishes.
__global__ void k_means(const float* __restrict__ y,
                        const float* __restrict__ x0,
                        const float* __restrict__ x1,
                        const float* __restrict__ x2,
                        const float* __restrict__ x3) {
    int warp = (blockIdx.x * blockDim.x + threadIdx.x) >> 5;
    int lane = threadIdx.x & 31;
    if (warp >= B_ * FEAT_) return;
    int b = warp / FEAT_;
    int j = warp - b * FEAT_;       // slot*256 + c
    int slot = j >> 8;
    int c = j & 255;
    const float* base;
    switch (slot) {
        case 0: base = y;  break;
        case 1: base = x0; break;
        case 2: base = x1; break;
        case 3: base = x2; break;
        default: base = x3; break;
    }
    const float4* p = reinterpret_cast<const float4*>(base + (size_t)(b * C_ + c) * HW_);
    float s = 0.f;
#pragma unroll
    for (int i = 0; i < 8; i++) {        // 8 * 32 lanes * 4 floats = 1024
        float4 v = p[lane + i * 32];
        s += (v.x + v.y) + (v.z + v.w);
    }
#pragma unroll
    for (int o = 16; o; o >>= 1) s += __shfl_xor_sync(0xffffffffu, s, o);
    if (lane == 0) g_feats[warp] = s * (1.0f / 1024.0f);
}

// ---------------- Kernel 2: gate MLP (GEMM -> BN -> ReLU -> GEMM -> act) ----------------
// One block per batch element. 256 threads.
__global__ void k_gate(const float* __restrict__ conv1_w,   // [32,1280]
                       const float* __restrict__ bn_gamma,
                       const float* __restrict__ bn_beta,
                       const float* __restrict__ bn_mean,
                       const float* __restrict__ bn_var,
                       const float* __restrict__ conv2_w,   // [1280,32]
                       const float* __restrict__ conv2_b) { // [1280]
    __shared__ float sf[FEAT_];
    __shared__ float sh[MID_];
    int b = blockIdx.x;
    int t = threadIdx.x;

    for (int i = t; i < FEAT_; i += 256) sf[i] = g_feats[b * FEAT_ + i];
    __syncthreads();

    int warp = t >> 5, lane = t & 31;
    // GEMM1: each warp computes 4 of the 32 mid channels
#pragma unroll
    for (int mi = 0; mi < 4; mi++) {
        int mid = warp * 4 + mi;
        const float* wr = conv1_w + mid * FEAT_;
        float s = 0.f;
#pragma unroll
        for (int j0 = 0; j0 < FEAT_; j0 += 32) s = fmaf(sf[j0 + lane], wr[j0 + lane], s);
#pragma unroll
        for (int o = 16; o; o >>= 1) s += __shfl_xor_sync(0xffffffffu, s, o);
        if (lane == 0) {
            float hv = (s - bn_mean[mid]) * (bn_gamma[mid] * rsqrtf(bn_var[mid] + 1e-5f))
                       + bn_beta[mid];
            sh[mid] = fmaxf(hv, 0.f);
        }
    }
    __syncthreads();

    // GEMM2: thread t owns channel c=t across all 5 slots (j = m*256 + t)
    float v[5];
#pragma unroll
    for (int m = 0; m < 5; m++) {
        int j = m * 256 + t;
        float s = conv2_b[j];
        const float* wr = conv2_w + j * MID_;
#pragma unroll
        for (int mid = 0; mid < MID_; mid++) s = fmaf(sh[mid], wr[mid], s);
        v[m] = s;
    }
    // slot 0 -> sigmoid self gate
    g_w1[b * C_ + t] = 1.0f / (1.0f + expf(-v[0]));
    // slots 1..4 -> softmax over K
    float mx = fmaxf(fmaxf(v[1], v[2]), fmaxf(v[3], v[4]));
    float e1 = expf(v[1] - mx), e2 = expf(v[2] - mx);
    float e3 = expf(v[3] - mx), e4 = expf(v[4] - mx);
    float inv = 1.0f / (e1 + e2 + e3 + e4);
    int base = b * K_ * C_ + t;
    g_w2[base + 0 * C_] = e1 * inv;
    g_w2[base + 1 * C_] = e2 * inv;
    g_w2[base + 2 * C_] = e3 * inv;
    g_w2[base + 3 * C_] = e4 * inv;
}

// ---------------- Kernel 3: apply gates (streaming, float4, REVERSED traversal) ------
// Reversed block order: starts on the address tail that k_means just left in L2.
// Streaming loads/stores (.cs) so dead data doesn't displace the reusable tail.
__global__ void k_apply(const float* __restrict__ y,
                        const float* __restrict__ x0,
                        const float* __restrict__ x1,
                        const float* __restrict__ x2,
                        const float* __restrict__ x3,
                        float* __restrict__ out) {
    int blk = gridDim.x - 1 - blockIdx.x;            // reversed
    int i = blk * blockDim.x + threadIdx.x;          // float4 index, total 2097152
    int bc = i >> 8;                                 // 256 float4 per (b,c) row
    int b = bc >> 8;
    int c = bc & 255;
    float w1 = g_w1[bc];
    int base = b * K_ * C_ + c;
    float a0 = g_w2[base + 0 * C_];
    float a1 = g_w2[base + 1 * C_];
    float a2 = g_w2[base + 2 * C_];
    float a3 = g_w2[base + 3 * C_];

    float4 yv = __ldcs(reinterpret_cast<const float4*>(y) + i);
    float4 v0 = __ldcs(reinterpret_cast<const float4*>(x0) + i);
    float4 v1 = __ldcs(reinterpret_cast<const float4*>(x1) + i);
    float4 v2 = __ldcs(reinterpret_cast<const float4*>(x2) + i);
    float4 v3 = __ldcs(reinterpret_cast<const float4*>(x3) + i);

    float4 r;
    r.x = fmaf(yv.x, w1, fmaf(a0, v0.x, fmaf(a1, v1.x, fmaf(a2, v2.x, a3 * v3.x))));
    r.y = fmaf(yv.y, w1, fmaf(a0, v0.y, fmaf(a1, v1.y, fmaf(a2, v2.y, a3 * v3.y))));
    r.z = fmaf(yv.z, w1, fmaf(a0, v0.z, fmaf(a1, v1.z, fmaf(a2, v2.z, a3 * v3.z))));
    r.w = fmaf(yv.w, w1, fmaf(a0, v0.w, fmaf(a1, v1.w, fmaf(a2, v2.w, a3 * v3.w))));
    __stcs(reinterpret_cast<float4*>(out) + i, r);
}

extern "C" void kernel_launch(void* const* d_in, const int* in_sizes, int n_in,
                              void* d_out, int out_size) {
    const float* y       = (const float*)d_in[0];
    const float* x0      = (const float*)d_in[1];
    const float* x1      = (const float*)d_in[2];
    const float* x2      = (const float*)d_in[3];
    const float* x3      = (const float*)d_in[4];
    const float* conv1_w = (const float*)d_in[5];
    const float* bn_g    = (const float*)d_in[6];
    const float* bn_b    = (const float*)d_in[7];
    const float* bn_m    = (const float*)d_in[8];
    const float* bn_v    = (const float*)d_in[9];
    const float* conv2_w = (const float*)d_in[10];
    const float* conv2_b = (const float*)d_in[11];
    float* out = (float*)d_out;

    // 40960 warps, 8 warps/block -> 5120 blocks
    k_means<<<5120, 256>>>(y, x0, x1, x2, x3);
    k_gate<<<32, 256>>>(conv1_w, bn_g, bn_b, bn_m, bn_v, conv2_w, conv2_b);
    // 2097152 float4 / 256 threads -> 8192 blocks, reversed inside the kernel
    k_apply<<<8192, 256>>>(y, x0, x1, x2, x3, out);
}